// round 13
// baseline (speedup 1.0000x reference)
#include <cuda_runtime.h>
#include <cuda_fp16.h>
#include <cstdint>

#define N_NODES 50000
#define N_EDGES 1600000
#define F 48
#define NREL 8

// transform tiling (tensor-core version, all 8 rels per block)
#define NT 128          // nodes per block
#define TPB1 256        // 8 warps x 16 rows
#define SXP 56          // sX/sH row stride (halfs): 112B rows, conflict-free ldmatrix
#define SWP 56          // sW row stride (halfs)
#define NTILES ((N_NODES + NT - 1) / NT)      // 391 transform blocks

// build
#define EPB_B 256
#define BBLOCKS (N_EDGES / EPB_B)             // 6250 build blocks

// fused grid: period 17 -> 1 transform + 16 build blocks
#define FUSED_GRID (NTILES * 17)              // 6647 (6 build spares return)

// bucketed CSR
#define CAP 128         // max edges per dst bucket (Poisson(32), max~63 over 50k)

// agg config: 6 lanes x 16B per edge
#define GPB 64                            // dst nodes per block
#define TPBA 192                          // 32 groups x 6 lanes

typedef unsigned long long u64;

// ------------------------- static device scratch ---------------------------
// h2 stored as fp16: 50000*8*48*2B = 38.4 MB -> L2-resident
__device__ __align__(16) __half g_h2h[(size_t)N_NODES * NREL * F];
__device__ int   g_counts[N_NODES];     // zero-init at load; agg re-zeroes each run
__device__ u64   g_recs[(size_t)N_NODES * CAP];   // {norm:f32 hi, srel:u32 lo}

// ------------------------------ PTX helpers --------------------------------
__device__ __forceinline__ uint32_t smem_u32(const void* p) {
    uint32_t a;
    asm("{ .reg .u64 t; cvta.to.shared.u64 t, %1; cvt.u32.u64 %0, t; }"
        : "=r"(a) : "l"(p));
    return a;
}
__device__ __forceinline__ void ldm_x4(uint32_t& r0, uint32_t& r1,
                                       uint32_t& r2, uint32_t& r3, uint32_t addr) {
    asm volatile("ldmatrix.sync.aligned.m8n8.x4.shared.b16 {%0,%1,%2,%3}, [%4];"
                 : "=r"(r0), "=r"(r1), "=r"(r2), "=r"(r3) : "r"(addr));
}
__device__ __forceinline__ void ldm_x2_trans(uint32_t& r0, uint32_t& r1, uint32_t addr) {
    asm volatile("ldmatrix.sync.aligned.m8n8.x2.trans.shared.b16 {%0,%1}, [%2];"
                 : "=r"(r0), "=r"(r1) : "r"(addr));
}
__device__ __forceinline__ void mma16816(float* c, const uint32_t* a, const uint32_t* b) {
    asm volatile(
        "mma.sync.aligned.m16n8k16.row.col.f32.f16.f16.f32 "
        "{%0,%1,%2,%3},{%4,%5,%6,%7},{%8,%9},{%0,%1,%2,%3};"
        : "+f"(c[0]), "+f"(c[1]), "+f"(c[2]), "+f"(c[3])
        : "r"(a[0]), "r"(a[1]), "r"(a[2]), "r"(a[3]), "r"(b[0]), "r"(b[1]));
}

// ---------------------------------------------------------------------------
// Transform block body: for ALL 8 rels, h2[n,r,:] = relu(x@W1[r]+b1)@W2[r].
// x staged once; phase-1 A-fragments hoisted once (sX is read-only here,
// h1 goes to the separate sH buffer). Per rel: restage W (L2-hot), 2 MMA
// phases, fp16 h2 store.
// ---------------------------------------------------------------------------
__device__ __forceinline__ void transform_body(
    int ntile,
    const float* __restrict__ x, const float* __restrict__ W1,
    const float* __restrict__ W2, const float* __restrict__ b1)
{
    __shared__ __align__(16) __half sX[NT][SXP];   // x fp16 (read-only after stage)
    __shared__ __align__(16) __half sH[NT][SXP];   // h1 fp16 per rel
    __shared__ __align__(16) __half sW1h[F][SWP];
    __shared__ __align__(16) __half sW2h[F][SWP];

    const int n0b  = ntile * NT;
    const int tid  = threadIdx.x;
    const int warp = tid >> 5;
    const int lane = tid & 31;

    // ---- stage x once (fp32 -> fp16), vectorized, zero-pad OOB rows ----
    for (int idx = tid; idx < NT * F / 4; idx += TPB1) {
        int row = idx / (F / 4);
        int c4  = (idx % (F / 4)) * 4;
        int gn  = n0b + row;
        float4 v = (gn < N_NODES)
            ? *reinterpret_cast<const float4*>(&x[(size_t)gn * F + c4])
            : make_float4(0.f, 0.f, 0.f, 0.f);
        *reinterpret_cast<__half2*>(&sX[row][c4])     = __floats2half2_rn(v.x, v.y);
        *reinterpret_cast<__half2*>(&sX[row][c4 + 2]) = __floats2half2_rn(v.z, v.w);
    }
    __syncthreads();

    const uint32_t sx_base  = smem_u32(&sX[0][0]);
    const uint32_t sh_base  = smem_u32(&sH[0][0]);
    const uint32_t sw1_base = smem_u32(&sW1h[0][0]);
    const uint32_t sw2_base = smem_u32(&sW2h[0][0]);

    const int arow = warp * 16 + (lane & 15);         // ldmatrix A row
    const int acol = (lane >> 4) * 8;                 // 0 or 8
    const int g4   = lane >> 2;                       // C row within 8
    const int t4   = lane & 3;                        // C col pair

    // hoist phase-1 A fragments: constant across all rels
    uint32_t a1f[3][4];
    #pragma unroll
    for (int kk = 0; kk < 3; kk++) {
        uint32_t addr = sx_base + (uint32_t)((arow * SXP + acol + kk * 16) * 2);
        ldm_x4(a1f[kk][0], a1f[kk][1], a1f[kk][2], a1f[kk][3], addr);
    }

    for (int r = 0; r < NREL; r++) {
        // all warps done reading sW of the previous rel
        __syncthreads();
        const size_t wbase = (size_t)r * F * F;
        for (int idx = tid; idx < F * F; idx += TPB1) {
            sW1h[idx / F][idx % F] = __float2half(W1[wbase + idx]);
            sW2h[idx / F][idx % F] = __float2half(W2[wbase + idx]);
        }
        __syncthreads();

        float c[6][4];

        // ============ phase 1: h1 = relu(x @ W1 + b1) ============
        #pragma unroll
        for (int t = 0; t < 6; t++)
            #pragma unroll
            for (int i = 0; i < 4; i++) c[t][i] = 0.f;

        #pragma unroll
        for (int t = 0; t < 6; t++) {
            const int n0 = t * 8;
            #pragma unroll
            for (int kk = 0; kk < 3; kk++) {
                uint32_t b[2];
                uint32_t addr = sw1_base + (uint32_t)(((kk * 16 + (lane & 15)) * SWP + n0) * 2);
                ldm_x2_trans(b[0], b[1], addr);
                mma16816(c[t], a1f[kk], b);
            }
        }

        // epilogue 1: bias + relu, pack fp16 into sH (warp-local rows)
        {
            const int row0 = warp * 16 + g4;
            #pragma unroll
            for (int t = 0; t < 6; t++) {
                const int col = t * 8 + 2 * t4;
                float bx = __ldg(&b1[col]);
                float by = __ldg(&b1[col + 1]);
                *reinterpret_cast<__half2*>(&sH[row0][col]) =
                    __floats2half2_rn(fmaxf(c[t][0] + bx, 0.f), fmaxf(c[t][1] + by, 0.f));
                *reinterpret_cast<__half2*>(&sH[row0 + 8][col]) =
                    __floats2half2_rn(fmaxf(c[t][2] + bx, 0.f), fmaxf(c[t][3] + by, 0.f));
            }
        }
        __syncwarp();   // warp-local handoff

        // ============ phase 2: h2 = h1 @ W2 ============
        uint32_t a2f[3][4];
        #pragma unroll
        for (int kk = 0; kk < 3; kk++) {
            uint32_t addr = sh_base + (uint32_t)((arow * SXP + acol + kk * 16) * 2);
            ldm_x4(a2f[kk][0], a2f[kk][1], a2f[kk][2], a2f[kk][3], addr);
        }
        #pragma unroll
        for (int t = 0; t < 6; t++)
            #pragma unroll
            for (int i = 0; i < 4; i++) c[t][i] = 0.f;

        #pragma unroll
        for (int t = 0; t < 6; t++) {
            const int n0 = t * 8;
            #pragma unroll
            for (int kk = 0; kk < 3; kk++) {
                uint32_t b[2];
                uint32_t addr = sw2_base + (uint32_t)(((kk * 16 + (lane & 15)) * SWP + n0) * 2);
                ldm_x2_trans(b[0], b[1], addr);
                mma16816(c[t], a2f[kk], b);
            }
        }

        // epilogue 2: store h2 fp16
        {
            const int gn0 = n0b + warp * 16 + g4;
            const int gn1 = gn0 + 8;
            #pragma unroll
            for (int t = 0; t < 6; t++) {
                const int col = t * 8 + 2 * t4;
                if (gn0 < N_NODES)
                    *reinterpret_cast<__half2*>(
                        &g_h2h[((size_t)gn0 * NREL + r) * F + col]) =
                        __floats2half2_rn(c[t][0], c[t][1]);
                if (gn1 < N_NODES)
                    *reinterpret_cast<__half2*>(
                        &g_h2h[((size_t)gn1 * NREL + r) * F + col]) =
                        __floats2half2_rn(c[t][2], c[t][3]);
            }
        }
    }
}

// ---------------------------------------------------------------------------
// Build block body: hist rank (atomicAdd return) + direct bucketed scatter.
// ---------------------------------------------------------------------------
__device__ __forceinline__ void build_body(
    int bld,
    const int* __restrict__ src, const int* __restrict__ dst,
    const int* __restrict__ rel, const float* __restrict__ norm)
{
    int e = bld * EPB_B + threadIdx.x;
    if (e >= N_EDGES) return;
    int d = dst[e];
    int rank = atomicAdd(&g_counts[d], 1);
    if (rank < CAP) {
        uint32_t srel = (uint32_t)src[e] * NREL + (uint32_t)rel[e];
        uint32_t wb = __float_as_uint(norm[e]);
        g_recs[(size_t)d * CAP + rank] = ((u64)wb << 32) | (u64)srel;
    }
}

// ---------------------------------------------------------------------------
// Fused kernel: bid%17==0 -> transform (all 8 rels), else -> build chunk.
// ---------------------------------------------------------------------------
__global__ __launch_bounds__(TPB1) void fused_kernel(
    const float* __restrict__ x, const float* __restrict__ W1,
    const float* __restrict__ W2, const float* __restrict__ b1,
    const int* __restrict__ src, const int* __restrict__ dst,
    const int* __restrict__ rel, const float* __restrict__ norm)
{
    const int bid = blockIdx.x;
    const int m   = bid % 17;
    if (m == 0) {
        transform_body(bid / 17, x, W1, W2, b1);
    } else {
        const int bld = (bid / 17) * 16 + (m - 1);
        if (bld < BBLOCKS) build_body(bld, src, dst, rel, norm);
    }
}

// ---------------------------------------------------------------------------
// Aggregation: 32 groups x 6 lanes per block; lane owns 16B (8 halfs) of the
// row -> uint4 gather (half the load instructions of the 12-lane version).
// 2-edge double-buffered pipeline; fused bias2+relu store; count reset.
// ---------------------------------------------------------------------------
__device__ __forceinline__ uint4 gather16(u64 rec, int k)
{
    return *reinterpret_cast<const uint4*>(
        &g_h2h[(size_t)(uint32_t)rec * F + k * 8]);
}
__device__ __forceinline__ void consume16(float4& a0, float4& a1, u64 rec, uint4 p)
{
    float w = __uint_as_float((uint32_t)(rec >> 32));
    float2 f0 = __half22float2(*reinterpret_cast<__half2*>(&p.x));
    float2 f1 = __half22float2(*reinterpret_cast<__half2*>(&p.y));
    float2 f2 = __half22float2(*reinterpret_cast<__half2*>(&p.z));
    float2 f3 = __half22float2(*reinterpret_cast<__half2*>(&p.w));
    a0.x += f0.x * w; a0.y += f0.y * w;
    a0.z += f1.x * w; a0.w += f1.y * w;
    a1.x += f2.x * w; a1.y += f2.y * w;
    a1.z += f3.x * w; a1.w += f3.y * w;
}

__global__ __launch_bounds__(TPBA) void agg_kernel(
    const float* __restrict__ b2, float* __restrict__ out)
{
    const int tid  = threadIdx.x;
    const int grp  = tid / 6;          // 32 groups
    const int k    = tid % 6;          // 16B slot
    const int base = blockIdx.x * GPB;

    const float4 bv0 = reinterpret_cast<const float4*>(b2)[k * 2];
    const float4 bv1 = reinterpret_cast<const float4*>(b2)[k * 2 + 1];

    #pragma unroll
    for (int nn = 0; nn < GPB / 32; nn++) {
        const int g = base + grp + nn * 32;
        if (g >= N_NODES) break;

        int len = g_counts[g];
        if (len > CAP) len = CAP;
        const u64* recs = &g_recs[(size_t)g * CAP];

        float4 x0 = make_float4(0.f, 0.f, 0.f, 0.f);
        float4 x1 = make_float4(0.f, 0.f, 0.f, 0.f);
        float4 y0 = make_float4(0.f, 0.f, 0.f, 0.f);
        float4 y1 = make_float4(0.f, 0.f, 0.f, 0.f);

        int e = 0;
        if (len >= 4) {
            u64 r0 = recs[0], r1 = recs[1];
            uint4 p0 = gather16(r0, k), p1 = gather16(r1, k);
            e = 2;
            for (; e + 1 < len; e += 2) {
                u64 r2 = recs[e], r3 = recs[e + 1];
                uint4 p2 = gather16(r2, k), p3 = gather16(r3, k);
                consume16(x0, x1, r0, p0);
                consume16(y0, y1, r1, p1);
                r0 = r2; r1 = r3; p0 = p2; p1 = p3;
            }
            consume16(x0, x1, r0, p0);
            consume16(y0, y1, r1, p1);
        }
        for (; e < len; e++) {
            u64 rr = recs[e];
            consume16(x0, x1, rr, gather16(rr, k));
        }

        float4 o0, o1;
        o0.x = fmaxf(x0.x + y0.x + bv0.x, 0.f);
        o0.y = fmaxf(x0.y + y0.y + bv0.y, 0.f);
        o0.z = fmaxf(x0.z + y0.z + bv0.z, 0.f);
        o0.w = fmaxf(x0.w + y0.w + bv0.w, 0.f);
        o1.x = fmaxf(x1.x + y1.x + bv1.x, 0.f);
        o1.y = fmaxf(x1.y + y1.y + bv1.y, 0.f);
        o1.z = fmaxf(x1.z + y1.z + bv1.z, 0.f);
        o1.w = fmaxf(x1.w + y1.w + bv1.w, 0.f);
        float4* op = reinterpret_cast<float4*>(&out[(size_t)g * F + k * 8]);
        op[0] = o0;
        op[1] = o1;
    }

    // reset counts for the next replay
    __syncthreads();
    int g = base + tid;
    if (tid < GPB && g < N_NODES) g_counts[g] = 0;
}

// ---------------------------------------------------------------------------
extern "C" void kernel_launch(void* const* d_in, const int* in_sizes, int n_in,
                              void* d_out, int out_size)
{
    const float* x    = (const float*)d_in[0];
    const float* norm = (const float*)d_in[1];
    const float* W1   = (const float*)d_in[2];
    const float* W2   = (const float*)d_in[3];
    const float* b1   = (const float*)d_in[4];
    const float* b2   = (const float*)d_in[5];
    const int*   src  = (const int*)d_in[6];
    const int*   dst  = (const int*)d_in[7];
    const int*   rel  = (const int*)d_in[8];
    float* out = (float*)d_out;

    // ---- fused build + transform (forced overlap in one launch) ----
    fused_kernel<<<FUSED_GRID, TPB1>>>(x, W1, W2, b1, src, dst, rel, norm);

    // ---- gather + reduce + bias + relu ----
    agg_kernel<<<(N_NODES + GPB - 1) / GPB, TPBA>>>(b2, out);
}

// round 14
// speedup vs baseline: 1.2199x; 1.2199x over previous
#include <cuda_runtime.h>
#include <cuda_fp16.h>
#include <cstdint>

#define N_NODES 50000
#define N_EDGES 1600000
#define F 48
#define NREL 8

// transform tiling (tensor-core version)
#define NT 128          // nodes per block
#define TPB1 256        // 8 warps x 16 rows
#define SXP 56          // sX/sH row stride (halfs): 112B rows, conflict-free ldmatrix
#define SWP 56          // sW row stride (halfs)
#define NTILES ((N_NODES + NT - 1) / NT)      // 391
#define TBLOCKS (NTILES * NREL)               // 3128 transform blocks

// build
#define EPB_B 256
#define BBLOCKS (N_EDGES / EPB_B)             // 6250 build blocks

// fused grid: bid%3==2 -> transform(bid/3), else -> build((bid/3)*2 + bid%3)
#define FUSED_GRID (3 * TBLOCKS)              // 9384 (build spares return)

// bucketed CSR
#define CAP 128         // max edges per dst bucket (Poisson(32), max~63 over 50k)

// agg config: grid-doubled for occupancy (latency-bound kernel)
#define GPB 32                            // dst nodes per block -> grid 1563
#define NGRP 16                           // 12-lane groups per block
#define TPBA 192

typedef unsigned long long u64;

// ------------------------- static device scratch ---------------------------
// h2 stored as fp16: 50000*8*48*2B = 38.4 MB -> L2-resident
__device__ __align__(16) __half g_h2h[(size_t)N_NODES * NREL * F];
__device__ int   g_counts[N_NODES];     // zero-init at load; agg re-zeroes each run
__device__ u64   g_recs[(size_t)N_NODES * CAP];   // {norm:f32 hi, srel:u32 lo}

// ------------------------------ PTX helpers --------------------------------
__device__ __forceinline__ uint32_t smem_u32(const void* p) {
    uint32_t a;
    asm("{ .reg .u64 t; cvta.to.shared.u64 t, %1; cvt.u32.u64 %0, t; }"
        : "=r"(a) : "l"(p));
    return a;
}
__device__ __forceinline__ void ldm_x4(uint32_t& r0, uint32_t& r1,
                                       uint32_t& r2, uint32_t& r3, uint32_t addr) {
    asm volatile("ldmatrix.sync.aligned.m8n8.x4.shared.b16 {%0,%1,%2,%3}, [%4];"
                 : "=r"(r0), "=r"(r1), "=r"(r2), "=r"(r3) : "r"(addr));
}
__device__ __forceinline__ void ldm_x2_trans(uint32_t& r0, uint32_t& r1, uint32_t addr) {
    asm volatile("ldmatrix.sync.aligned.m8n8.x2.trans.shared.b16 {%0,%1}, [%2];"
                 : "=r"(r0), "=r"(r1) : "r"(addr));
}
__device__ __forceinline__ void mma16816(float* c, const uint32_t* a, const uint32_t* b) {
    asm volatile(
        "mma.sync.aligned.m16n8k16.row.col.f32.f16.f16.f32 "
        "{%0,%1,%2,%3},{%4,%5,%6,%7},{%8,%9},{%0,%1,%2,%3};"
        : "+f"(c[0]), "+f"(c[1]), "+f"(c[2]), "+f"(c[3])
        : "r"(a[0]), "r"(a[1]), "r"(a[2]), "r"(a[3]), "r"(b[0]), "r"(b[1]));
}

// ---------------------------------------------------------------------------
// Transform block body (HMMA): h2[n,r,:] = relu(x[n] @ W1[r] + b1) @ W2[r]
// ---------------------------------------------------------------------------
__device__ __forceinline__ void transform_body(
    int ntile, int r,
    const float* __restrict__ x, const float* __restrict__ W1,
    const float* __restrict__ W2, const float* __restrict__ b1)
{
    __shared__ __align__(16) __half sX[NT][SXP];   // x fp16, reused as h1 fp16
    __shared__ __align__(16) __half sW1h[F][SWP];
    __shared__ __align__(16) __half sW2h[F][SWP];

    const int n0b  = ntile * NT;
    const int tid  = threadIdx.x;
    const int warp = tid >> 5;
    const int lane = tid & 31;

    // ---- stage weights (fp32 -> fp16) ----
    const size_t wbase = (size_t)r * F * F;
    for (int idx = tid; idx < F * F; idx += TPB1) {
        sW1h[idx / F][idx % F] = __float2half(W1[wbase + idx]);
        sW2h[idx / F][idx % F] = __float2half(W2[wbase + idx]);
    }
    // ---- stage x (fp32 -> fp16), vectorized, zero-pad OOB rows ----
    for (int idx = tid; idx < NT * F / 4; idx += TPB1) {
        int row = idx / (F / 4);
        int c4  = (idx % (F / 4)) * 4;
        int gn  = n0b + row;
        float4 v = (gn < N_NODES)
            ? *reinterpret_cast<const float4*>(&x[(size_t)gn * F + c4])
            : make_float4(0.f, 0.f, 0.f, 0.f);
        *reinterpret_cast<__half2*>(&sX[row][c4])     = __floats2half2_rn(v.x, v.y);
        *reinterpret_cast<__half2*>(&sX[row][c4 + 2]) = __floats2half2_rn(v.z, v.w);
    }
    __syncthreads();

    const uint32_t sx_base  = smem_u32(&sX[0][0]);
    const uint32_t sw1_base = smem_u32(&sW1h[0][0]);
    const uint32_t sw2_base = smem_u32(&sW2h[0][0]);

    const int arow = warp * 16 + (lane & 15);         // ldmatrix A row
    const int acol = (lane >> 4) * 8;                 // 0 or 8
    const int g4   = lane >> 2;                       // C row within 8
    const int t4   = lane & 3;                        // C col pair

    uint32_t a[3][4];
    float    c[6][4];

    // =================== phase 1: h1 = relu(x @ W1 + b1) ===================
    #pragma unroll
    for (int kk = 0; kk < 3; kk++) {
        uint32_t addr = sx_base + (uint32_t)((arow * SXP + acol + kk * 16) * 2);
        ldm_x4(a[kk][0], a[kk][1], a[kk][2], a[kk][3], addr);
    }
    #pragma unroll
    for (int t = 0; t < 6; t++)
        #pragma unroll
        for (int i = 0; i < 4; i++) c[t][i] = 0.f;

    #pragma unroll
    for (int t = 0; t < 6; t++) {
        const int n0 = t * 8;
        #pragma unroll
        for (int kk = 0; kk < 3; kk++) {
            uint32_t b[2];
            uint32_t addr = sw1_base + (uint32_t)(((kk * 16 + (lane & 15)) * SWP + n0) * 2);
            ldm_x2_trans(b[0], b[1], addr);
            mma16816(c[t], a[kk], b);
        }
    }

    // epilogue 1: bias + relu, pack fp16 back into sX (same rows this warp owns)
    {
        const int row0 = warp * 16 + g4;
        #pragma unroll
        for (int t = 0; t < 6; t++) {
            const int col = t * 8 + 2 * t4;
            float bx = __ldg(&b1[col]);
            float by = __ldg(&b1[col + 1]);
            *reinterpret_cast<__half2*>(&sX[row0][col]) =
                __floats2half2_rn(fmaxf(c[t][0] + bx, 0.f), fmaxf(c[t][1] + by, 0.f));
            *reinterpret_cast<__half2*>(&sX[row0 + 8][col]) =
                __floats2half2_rn(fmaxf(c[t][2] + bx, 0.f), fmaxf(c[t][3] + by, 0.f));
        }
    }
    __syncwarp();   // warp-local handoff: stores above -> ldmatrix below

    // =================== phase 2: h2 = h1 @ W2 ===================
    #pragma unroll
    for (int kk = 0; kk < 3; kk++) {
        uint32_t addr = sx_base + (uint32_t)((arow * SXP + acol + kk * 16) * 2);
        ldm_x4(a[kk][0], a[kk][1], a[kk][2], a[kk][3], addr);
    }
    #pragma unroll
    for (int t = 0; t < 6; t++)
        #pragma unroll
        for (int i = 0; i < 4; i++) c[t][i] = 0.f;

    #pragma unroll
    for (int t = 0; t < 6; t++) {
        const int n0 = t * 8;
        #pragma unroll
        for (int kk = 0; kk < 3; kk++) {
            uint32_t b[2];
            uint32_t addr = sw2_base + (uint32_t)(((kk * 16 + (lane & 15)) * SWP + n0) * 2);
            ldm_x2_trans(b[0], b[1], addr);
            mma16816(c[t], a[kk], b);
        }
    }

    // epilogue 2: store h2 fp16
    {
        const int gn0 = n0b + warp * 16 + g4;
        const int gn1 = gn0 + 8;
        #pragma unroll
        for (int t = 0; t < 6; t++) {
            const int col = t * 8 + 2 * t4;
            if (gn0 < N_NODES)
                *reinterpret_cast<__half2*>(
                    &g_h2h[((size_t)gn0 * NREL + r) * F + col]) =
                    __floats2half2_rn(c[t][0], c[t][1]);
            if (gn1 < N_NODES)
                *reinterpret_cast<__half2*>(
                    &g_h2h[((size_t)gn1 * NREL + r) * F + col]) =
                    __floats2half2_rn(c[t][2], c[t][3]);
        }
    }
}

// ---------------------------------------------------------------------------
// Build block body: hist rank (atomicAdd return) + direct bucketed scatter.
// ---------------------------------------------------------------------------
__device__ __forceinline__ void build_body(
    int bld,
    const int* __restrict__ src, const int* __restrict__ dst,
    const int* __restrict__ rel, const float* __restrict__ norm)
{
    int e = bld * EPB_B + threadIdx.x;
    if (e >= N_EDGES) return;
    int d = dst[e];
    int rank = atomicAdd(&g_counts[d], 1);
    if (rank < CAP) {
        uint32_t srel = (uint32_t)src[e] * NREL + (uint32_t)rel[e];
        uint32_t wb = __float_as_uint(norm[e]);
        g_recs[(size_t)d * CAP + rank] = ((u64)wb << 32) | (u64)srel;
    }
}

// ---------------------------------------------------------------------------
// Fused kernel: heterogeneous blocks. bid%3==2 -> transform, else -> build.
// 2:1 interleave in bid order keeps latency-bound build blocks co-resident
// with issue-bound transform blocks on every SM (forced overlap, no streams).
// ---------------------------------------------------------------------------
__global__ __launch_bounds__(TPB1) void fused_kernel(
    const float* __restrict__ x, const float* __restrict__ W1,
    const float* __restrict__ W2, const float* __restrict__ b1,
    const int* __restrict__ src, const int* __restrict__ dst,
    const int* __restrict__ rel, const float* __restrict__ norm)
{
    const int bid = blockIdx.x;
    const int m   = bid % 3;
    if (m == 2) {
        const int tb = bid / 3;               // 0..TBLOCKS-1
        transform_body(tb / NREL, tb % NREL, x, W1, W2, b1);
    } else {
        const int bld = (bid / 3) * 2 + m;    // 0..6255 (spares return)
        if (bld < BBLOCKS) build_body(bld, src, dst, rel, norm);
    }
}

// ---------------------------------------------------------------------------
// Aggregation: 32 nodes/block (grid=1563 -> ~10 blocks/SM, occupancy-driven),
// 16 groups x 12 lanes, each group owns 2 nodes. 2-edge double-buffered
// gather pipeline. Fused bias2+relu store; resets g_counts for next replay.
// ---------------------------------------------------------------------------
__device__ __forceinline__ uint2 gather8(u64 rec, int k)
{
    return *reinterpret_cast<const uint2*>(
        &g_h2h[(size_t)(uint32_t)rec * F + k * 4]);
}
__device__ __forceinline__ void consume(float4& a, u64 rec, uint2 p)
{
    float w = __uint_as_float((uint32_t)(rec >> 32));
    __half2 ha = *reinterpret_cast<__half2*>(&p.x);
    __half2 hb = *reinterpret_cast<__half2*>(&p.y);
    float2 fa = __half22float2(ha);
    float2 fb = __half22float2(hb);
    a.x += fa.x * w; a.y += fa.y * w;
    a.z += fb.x * w; a.w += fb.y * w;
}

__global__ __launch_bounds__(TPBA) void agg_kernel(
    const float* __restrict__ b2, float* __restrict__ out)
{
    const int tid  = threadIdx.x;
    const int grp  = tid / 12;
    const int k    = tid % 12;
    const int base = blockIdx.x * GPB;

    const float4 bv = reinterpret_cast<const float4*>(b2)[k];

    #pragma unroll
    for (int nn = 0; nn < GPB / NGRP; nn++) {
        const int g = base + grp + nn * NGRP;
        if (g >= N_NODES) break;

        int len = g_counts[g];
        if (len > CAP) len = CAP;
        const u64* recs = &g_recs[(size_t)g * CAP];

        float4 a0 = make_float4(0.f, 0.f, 0.f, 0.f);
        float4 a1 = make_float4(0.f, 0.f, 0.f, 0.f);

        int e = 0;
        if (len >= 4) {
            u64 r0 = recs[0], r1 = recs[1];
            uint2 p0 = gather8(r0, k), p1 = gather8(r1, k);
            e = 2;
            for (; e + 1 < len; e += 2) {
                u64 r2 = recs[e], r3 = recs[e + 1];
                uint2 p2 = gather8(r2, k), p3 = gather8(r3, k);
                consume(a0, r0, p0);
                consume(a1, r1, p1);
                r0 = r2; r1 = r3; p0 = p2; p1 = p3;
            }
            consume(a0, r0, p0);
            consume(a1, r1, p1);
        }
        for (; e < len; e++) {
            u64 rr = recs[e];
            consume(a0, rr, gather8(rr, k));
        }

        float4 o;
        o.x = fmaxf(a0.x + a1.x + bv.x, 0.f);
        o.y = fmaxf(a0.y + a1.y + bv.y, 0.f);
        o.z = fmaxf(a0.z + a1.z + bv.z, 0.f);
        o.w = fmaxf(a0.w + a1.w + bv.w, 0.f);
        *reinterpret_cast<float4*>(&out[(size_t)g * F + k * 4]) = o;
    }

    // reset counts for the next replay (all groups are done reading their
    // nodes' counts only after the block-wide barrier)
    __syncthreads();
    int g = base + tid;
    if (tid < GPB && g < N_NODES) g_counts[g] = 0;
}

// ---------------------------------------------------------------------------
extern "C" void kernel_launch(void* const* d_in, const int* in_sizes, int n_in,
                              void* d_out, int out_size)
{
    const float* x    = (const float*)d_in[0];
    const float* norm = (const float*)d_in[1];
    const float* W1   = (const float*)d_in[2];
    const float* W2   = (const float*)d_in[3];
    const float* b1   = (const float*)d_in[4];
    const float* b2   = (const float*)d_in[5];
    const int*   src  = (const int*)d_in[6];
    const int*   dst  = (const int*)d_in[7];
    const int*   rel  = (const int*)d_in[8];
    float* out = (float*)d_out;

    // ---- fused build + transform (forced overlap in one launch) ----
    fused_kernel<<<FUSED_GRID, TPB1>>>(x, W1, W2, b1, src, dst, rel, norm);

    // ---- gather + reduce + bias + relu ----
    agg_kernel<<<(N_NODES + GPB - 1) / GPB, TPBA>>>(b2, out);
}